// round 2
// baseline (speedup 1.0000x reference)
#include <cuda_runtime.h>

// InstHead fused, fp32, f32x2 FMA, two passes.
// R2: LDS.128 x-broadcasts (8/pt), tiny projections via SMEM-broadcast weights,
//     register caps for occupancy.

#define C 32
#define WPB 4
typedef unsigned long long u64;

__device__ __forceinline__ u64 fma2(u64 a, u64 b, u64 c) {
    u64 d;
    asm("fma.rn.f32x2 %0, %1, %2, %3;" : "=l"(d) : "l"(a), "l"(b), "l"(c));
    return d;
}
__device__ __forceinline__ u64 pack2(float lo, float hi) {
    u64 d;
    asm("mov.b64 %0, {%1, %2};" : "=l"(d) : "f"(lo), "f"(hi));
    return d;
}
__device__ __forceinline__ float sum2(u64 a) {
    float l, h;
    asm("mov.b64 {%0, %1}, %2;" : "=f"(l), "=f"(h) : "l"(a));
    return l + h;
}

// ---- scratch (device globals) ----
__device__ float g_pool[64 * C];
__device__ float g_cnt[64];
__device__ float g_sumH[C];
__device__ float g_sumH2[C];
__device__ float g_w1f[C * C];
__device__ float g_b1f[C];

__global__ void zero_kernel(int B) {
    int t = threadIdx.x;
    for (int i = t; i < B * C; i += blockDim.x) g_pool[i] = 0.f;
    if (t < B) g_cnt[t] = 0.f;
    if (t < C) { g_sumH[t] = 0.f; g_sumH2[t] = 0.f; }
}

#define XPITCH 40   // floats per point row: 160B, 16B-aligned for LDS.128
#define YPITCH 34   // even -> 8B-aligned rows for LDS.64

// ================= PASS 1 =================
__global__ void __launch_bounds__(32 * WPB, 4) pass1_kernel(
    const float* __restrict__ feats, const int* __restrict__ bidx,
    const float* __restrict__ w1,  const float* __restrict__ b1,
    const float* __restrict__ mw1, const float* __restrict__ mb1,
    const float* __restrict__ mw2, const float* __restrict__ mb2,
    float* __restrict__ mask_out, int n, int tiles_total, int tpw)
{
    __shared__ float sx[WPB][32 * XPITCH];
    __shared__ float sm[WPB][32 * YPITCH];
    __shared__ int   sb[WPB][32];
    __shared__ float s_mw2[C];
    __shared__ float s_mb2;

    const int lane = threadIdx.x & 31;
    const int wi   = threadIdx.x >> 5;
    if (threadIdx.x < C) s_mw2[threadIdx.x] = mw2[threadIdx.x];
    if (threadIdx.x == 0) s_mb2 = mb2[0];
    __syncthreads();

    u64 w1p[16], mw1p[16];
#pragma unroll
    for (int kk = 0; kk < 16; kk++) {
        w1p[kk]  = pack2(w1[(2 * kk) * C + lane],  w1[(2 * kk + 1) * C + lane]);
        mw1p[kk] = pack2(mw1[(2 * kk) * C + lane], mw1[(2 * kk + 1) * C + lane]);
    }
    const float b1t  = b1[lane];
    const float mb1t = mb1[lane];

    float sumH = 0.f, sumH2 = 0.f, pacc = 0.f;
    int   pcnt = 0, cur_b = -1;

    const int gwid = blockIdx.x * WPB + wi;
    int t0 = gwid * tpw;
    int t1 = t0 + tpw; if (t1 > tiles_total) t1 = tiles_total;

    float* SX = sx[wi];
    float* SM = sm[wi];
    int*   SB = sb[wi];

    for (int tile = t0; tile < t1; tile++) {
        const int base = tile * 32;
        int valid = n - base; if (valid > 32) valid = 32;
        const int lim = valid * 8;
        const float4* src = (const float4*)(feats + (size_t)base * C);
#pragma unroll
        for (int j = 0; j < 8; j++) {
            int L = lane + 32 * j;
            float4 v = make_float4(0.f, 0.f, 0.f, 0.f);
            if (L < lim) v = src[L];
            *(float4*)&SX[(L >> 3) * XPITCH + 4 * (L & 7)] = v;
        }
        if (lane < valid) SB[lane] = bidx[base + lane];
        __syncwarp();

        for (int p = 0; p < valid; p++) {
            const float* xp = &SX[p * XPITCH];
            u64 h2a = pack2(b1t, 0.f),  h2b = pack2(0.f, 0.f);
            u64 m2a = pack2(mb1t, 0.f), m2b = pack2(0.f, 0.f);
#pragma unroll
            for (int j = 0; j < 8; j++) {
                ulonglong2 q = *(const ulonglong2*)&xp[4 * j];
                h2a = fma2(q.x, w1p[2 * j],      h2a);
                m2a = fma2(q.x, mw1p[2 * j],     m2a);
                h2b = fma2(q.y, w1p[2 * j + 1],  h2b);
                m2b = fma2(q.y, mw1p[2 * j + 1], m2b);
            }
            float h = sum2(h2a) + sum2(h2b);
            sumH += h;
            sumH2 = fmaf(h, h, sumH2);
            SM[p * YPITCH + lane] = fmaxf(sum2(m2a) + sum2(m2b), 0.f);

            int b = SB[p];
            if (b != cur_b) {
                if (cur_b >= 0) {
                    atomicAdd(&g_pool[cur_b * C + lane], pacc);
                    if (lane == 0) atomicAdd(&g_cnt[cur_b], (float)pcnt);
                }
                cur_b = b; pacc = 0.f; pcnt = 0;
            }
            pacc += xp[lane];
            pcnt++;
        }
        __syncwarp();
        // mask projection: lane = point, weights broadcast from SMEM
        if (lane < valid) {
            const float* mr = &SM[lane * YPITCH];
            u64 a0 = pack2(s_mb2, 0.f);
#pragma unroll
            for (int k = 0; k < 16; k++) {
                u64 y2 = *(const u64*)&mr[2 * k];
                u64 w2 = *(const u64*)&s_mw2[2 * k];
                a0 = fma2(y2, w2, a0);
            }
            mask_out[base + lane] = sum2(a0);
        }
        __syncwarp();
    }

    if (cur_b >= 0) {
        atomicAdd(&g_pool[cur_b * C + lane], pacc);
        if (lane == 0) atomicAdd(&g_cnt[cur_b], (float)pcnt);
    }
    atomicAdd(&g_sumH[lane], sumH);
    atomicAdd(&g_sumH2[lane], sumH2);
}

// ================= FINALIZE =================
__global__ void finalize_kernel(
    const float* __restrict__ w1, const float* __restrict__ b1,
    const float* __restrict__ gamma, const float* __restrict__ beta,
    const float* __restrict__ iou_w, const float* __restrict__ iou_b,
    float* __restrict__ out_pooled, float* __restrict__ out_iou,
    int n, int B)
{
    int t = threadIdx.x;  // 0..31 channel
    float inv = 1.f / (float)n;
    float mu  = g_sumH[t] * inv;
    float var = g_sumH2[t] * inv - mu * mu;
    float s   = gamma[t] * rsqrtf(var + 1e-4f);
    g_b1f[t] = beta[t] + (b1[t] - mu) * s;
#pragma unroll
    for (int k = 0; k < C; k++) g_w1f[k * C + t] = w1[k * C + t] * s;

    float iw = iou_w[t];
    for (int b = 0; b < B; b++) {
        float cnt = fmaxf(g_cnt[b], 1.f);
        float pm  = g_pool[b * C + t] / cnt;
        out_pooled[b * C + t] = pm;
        float v = pm * iw;
#pragma unroll
        for (int o = 16; o > 0; o >>= 1) v += __shfl_xor_sync(0xffffffffu, v, o);
        if (t == 0) out_iou[b] = v + iou_b[0];
    }
}

// ================= PASS 2 =================
__global__ void __launch_bounds__(32 * WPB, 6) pass2_kernel(
    const float* __restrict__ feats,
    const float* __restrict__ w2, const float* __restrict__ ob2,
    float* __restrict__ off_out, int n, int tiles_total, int tpw)
{
    __shared__ float sx[WPB][32 * XPITCH];
    __shared__ float sy[WPB][32 * YPITCH];
    __shared__ float s_w2c[3][C];   // w2 columns, packed pairs read as u64
    __shared__ float s_ob2[3];

    const int lane = threadIdx.x & 31;
    const int wi   = threadIdx.x >> 5;
    if (threadIdx.x < C) {
        s_w2c[0][threadIdx.x] = w2[threadIdx.x * 3 + 0];
        s_w2c[1][threadIdx.x] = w2[threadIdx.x * 3 + 1];
        s_w2c[2][threadIdx.x] = w2[threadIdx.x * 3 + 2];
    }
    if (threadIdx.x < 3) s_ob2[threadIdx.x] = ob2[threadIdx.x];
    __syncthreads();

    u64 w1p[16];
#pragma unroll
    for (int kk = 0; kk < 16; kk++)
        w1p[kk] = pack2(g_w1f[(2 * kk) * C + lane], g_w1f[(2 * kk + 1) * C + lane]);
    const float b1t = g_b1f[lane];

    const int gwid = blockIdx.x * WPB + wi;
    int t0 = gwid * tpw;
    int t1 = t0 + tpw; if (t1 > tiles_total) t1 = tiles_total;

    float* SX = sx[wi];
    float* SY = sy[wi];

    for (int tile = t0; tile < t1; tile++) {
        const int base = tile * 32;
        int valid = n - base; if (valid > 32) valid = 32;
        const int lim = valid * 8;
        const float4* src = (const float4*)(feats + (size_t)base * C);
#pragma unroll
        for (int j = 0; j < 8; j++) {
            int L = lane + 32 * j;
            float4 v = make_float4(0.f, 0.f, 0.f, 0.f);
            if (L < lim) v = src[L];
            *(float4*)&SX[(L >> 3) * XPITCH + 4 * (L & 7)] = v;
        }
        __syncwarp();

        for (int p = 0; p < valid; p++) {
            const float* xp = &SX[p * XPITCH];
            u64 h2a = pack2(b1t, 0.f), h2b = pack2(0.f, 0.f);
#pragma unroll
            for (int j = 0; j < 8; j++) {
                ulonglong2 q = *(const ulonglong2*)&xp[4 * j];
                h2a = fma2(q.x, w1p[2 * j],     h2a);
                h2b = fma2(q.y, w1p[2 * j + 1], h2b);
            }
            SY[p * YPITCH + lane] = fmaxf(sum2(h2a) + sum2(h2b), 0.f);
        }
        __syncwarp();

        if (lane < valid) {
            const float* yr = &SY[lane * YPITCH];
            u64 a0 = pack2(s_ob2[0], 0.f);
            u64 a1 = pack2(s_ob2[1], 0.f);
            u64 a2 = pack2(s_ob2[2], 0.f);
#pragma unroll
            for (int k = 0; k < 16; k++) {
                u64 y2 = *(const u64*)&yr[2 * k];
                a0 = fma2(y2, *(const u64*)&s_w2c[0][2 * k], a0);
                a1 = fma2(y2, *(const u64*)&s_w2c[1][2 * k], a1);
                a2 = fma2(y2, *(const u64*)&s_w2c[2][2 * k], a2);
            }
            size_t o = (size_t)(base + lane) * 3;
            off_out[o + 0] = sum2(a0);
            off_out[o + 1] = sum2(a1);
            off_out[o + 2] = sum2(a2);
        }
        __syncwarp();
    }
}

// ================= LAUNCH =================
extern "C" void kernel_launch(void* const* d_in, const int* in_sizes, int n_in,
                              void* d_out, int out_size) {
    const float* feats = (const float*)d_in[0];
    const int*   bidx  = (const int*)  d_in[1];
    const float* w1    = (const float*)d_in[2];
    const float* b1    = (const float*)d_in[3];
    const float* gamma = (const float*)d_in[4];
    const float* beta  = (const float*)d_in[5];
    const float* w2    = (const float*)d_in[6];
    const float* ob2   = (const float*)d_in[7];
    const float* mw1   = (const float*)d_in[8];
    const float* mb1   = (const float*)d_in[9];
    const float* mw2   = (const float*)d_in[10];
    const float* mb2   = (const float*)d_in[11];
    const float* iw    = (const float*)d_in[12];
    const float* ib    = (const float*)d_in[13];

    int n = in_sizes[1];
    int B = (out_size - 4 * n) / 33;
    if (B < 1) B = 1;
    if (B > 64) B = 64;

    float* out        = (float*)d_out;
    float* out_off    = out;
    float* out_mask   = out + (size_t)3 * n;
    float* out_pooled = out + (size_t)4 * n;
    float* out_iou    = out_pooled + (size_t)B * C;

    int tiles  = (n + 31) / 32;
    int blocks = 608;
    int warps  = blocks * WPB;
    int tpw    = (tiles + warps - 1) / warps;

    zero_kernel<<<1, 1024>>>(B);
    pass1_kernel<<<blocks, 32 * WPB>>>(feats, bidx, w1, b1, mw1, mb1, mw2, mb2,
                                       out_mask, n, tiles, tpw);
    finalize_kernel<<<1, 32>>>(w1, b1, gamma, beta, iw, ib,
                               out_pooled, out_iou, n, B);
    pass2_kernel<<<blocks, 32 * WPB>>>(feats, w2, ob2, out_off, n, tiles, tpw);
}

// round 3
// speedup vs baseline: 1.0884x; 1.0884x over previous
#include <cuda_runtime.h>

// InstHead fused, fp32. R3: 2-point x 2-channel warp split halves SMEM
// broadcast wavefronts per point. Two passes (BN barrier), BN folded into W1.

#define C 32
#define WPB 4
typedef unsigned long long u64;

__device__ __forceinline__ u64 fma2(u64 a, u64 b, u64 c) {
    u64 d;
    asm("fma.rn.f32x2 %0, %1, %2, %3;" : "=l"(d) : "l"(a), "l"(b), "l"(c));
    return d;
}
__device__ __forceinline__ u64 pack2(float lo, float hi) {
    u64 d;
    asm("mov.b64 %0, {%1, %2};" : "=l"(d) : "f"(lo), "f"(hi));
    return d;
}
__device__ __forceinline__ float sum2(u64 a) {
    float l, h;
    asm("mov.b64 {%0, %1}, %2;" : "=f"(l), "=f"(h) : "l"(a));
    return l + h;
}

// ---- scratch ----
__device__ float g_pool[64 * C];
__device__ float g_cnt[64];
__device__ float g_sumH[C];
__device__ float g_sumH2[C];
__device__ float g_w1f[C * C];
__device__ float g_b1f[C];

__global__ void zero_kernel(int B) {
    int t = threadIdx.x;
    for (int i = t; i < B * C; i += blockDim.x) g_pool[i] = 0.f;
    if (t < B) g_cnt[t] = 0.f;
    if (t < C) { g_sumH[t] = 0.f; g_sumH2[t] = 0.f; }
}

#define XPITCH 40   // 160B rows: p,p+1 rows offset 8 banks -> conflict-free 2-addr LDS.128
#define YPITCH 34

// ================= PASS 1 =================
__global__ void __launch_bounds__(32 * WPB, 2) pass1_kernel(
    const float* __restrict__ feats, const int* __restrict__ bidx,
    const float* __restrict__ w1,  const float* __restrict__ b1,
    const float* __restrict__ mw1, const float* __restrict__ mb1,
    const float* __restrict__ mw2, const float* __restrict__ mb2,
    float* __restrict__ mask_out, int n, int tiles_total, int tpw)
{
    __shared__ float sx[WPB][32 * XPITCH];
    __shared__ float sm[WPB][32 * YPITCH];
    __shared__ int   sb[WPB][32];
    __shared__ float s_mw2[C];
    __shared__ float s_mb2;

    const int lane = threadIdx.x & 31;
    const int wi   = threadIdx.x >> 5;
    const int hw   = lane >> 4;        // half-warp: which point of the pair
    const int sl   = lane & 15;
    const int c0   = 2 * sl;           // this lane's channel pair (c0, c0+1)

    if (threadIdx.x < C) s_mw2[threadIdx.x] = mw2[threadIdx.x];
    if (threadIdx.x == 0) s_mb2 = mb2[0];
    __syncthreads();

    // per-lane weights for 2 channels, both GEMMs: 64 u64
    u64 w1p0[16], w1p1[16], mw1p0[16], mw1p1[16];
#pragma unroll
    for (int kk = 0; kk < 16; kk++) {
        w1p0[kk]  = pack2(w1[(2 * kk) * C + c0],      w1[(2 * kk + 1) * C + c0]);
        w1p1[kk]  = pack2(w1[(2 * kk) * C + c0 + 1],  w1[(2 * kk + 1) * C + c0 + 1]);
        mw1p0[kk] = pack2(mw1[(2 * kk) * C + c0],     mw1[(2 * kk + 1) * C + c0]);
        mw1p1[kk] = pack2(mw1[(2 * kk) * C + c0 + 1], mw1[(2 * kk + 1) * C + c0 + 1]);
    }
    const float b10 = b1[c0],  b11 = b1[c0 + 1];
    const float mb0 = mb1[c0], mb1t = mb1[c0 + 1];
    const u64 kONE = pack2(1.f, 1.f);

    float sumH0 = 0.f, sumH20 = 0.f, sumH1 = 0.f, sumH21 = 0.f;
    u64   pacc  = pack2(0.f, 0.f);
    int   pcnt = 0, cur_b = -1;

    const int gwid = blockIdx.x * WPB + wi;
    int t0 = gwid * tpw;
    int t1 = t0 + tpw; if (t1 > tiles_total) t1 = tiles_total;

    float* SX = sx[wi];
    float* SM = sm[wi];
    int*   SB = sb[wi];

    for (int tile = t0; tile < t1; tile++) {
        const int base = tile * 32;
        int valid = n - base; if (valid > 32) valid = 32;
        const int lim = valid * 8;
        const float4* src = (const float4*)(feats + (size_t)base * C);
#pragma unroll
        for (int j = 0; j < 8; j++) {
            int L = lane + 32 * j;
            float4 v = make_float4(0.f, 0.f, 0.f, 0.f);
            if (L < lim) v = src[L];
            *(float4*)&SX[(L >> 3) * XPITCH + 4 * (L & 7)] = v;
        }
        if (lane < valid) SB[lane] = bidx[base + lane];
        __syncwarp();

#pragma unroll 2
        for (int i = 0; i < 16; i++) {
            const int p = 2 * i + hw;
            if (p < valid) {
                const float* xp = &SX[p * XPITCH];
                u64 h0a = pack2(b10, 0.f), h0b = pack2(0.f, 0.f);
                u64 h1a = pack2(b11, 0.f), h1b = pack2(0.f, 0.f);
                u64 m0a = pack2(mb0, 0.f), m0b = pack2(0.f, 0.f);
                u64 m1a = pack2(mb1t, 0.f), m1b = pack2(0.f, 0.f);
#pragma unroll
                for (int j = 0; j < 8; j++) {
                    ulonglong2 q = *(const ulonglong2*)&xp[4 * j];
                    h0a = fma2(q.x, w1p0[2 * j],      h0a);
                    h0b = fma2(q.y, w1p0[2 * j + 1],  h0b);
                    h1a = fma2(q.x, w1p1[2 * j],      h1a);
                    h1b = fma2(q.y, w1p1[2 * j + 1],  h1b);
                    m0a = fma2(q.x, mw1p0[2 * j],     m0a);
                    m0b = fma2(q.y, mw1p0[2 * j + 1], m0b);
                    m1a = fma2(q.x, mw1p1[2 * j],     m1a);
                    m1b = fma2(q.y, mw1p1[2 * j + 1], m1b);
                }
                float h0 = sum2(h0a) + sum2(h0b);
                float h1 = sum2(h1a) + sum2(h1b);
                sumH0 += h0; sumH20 = fmaf(h0, h0, sumH20);
                sumH1 += h1; sumH21 = fmaf(h1, h1, sumH21);
                float m0 = fmaxf(sum2(m0a) + sum2(m0b), 0.f);
                float m1 = fmaxf(sum2(m1a) + sum2(m1b), 0.f);
                *(u64*)&SM[p * YPITCH + c0] = pack2(m0, m1);

                int b = SB[p];
                if (b != cur_b) {
                    if (cur_b >= 0) {
                        float pl, ph;
                        asm("mov.b64 {%0, %1}, %2;" : "=f"(pl), "=f"(ph) : "l"(pacc));
                        atomicAdd(&g_pool[cur_b * C + c0],     pl);
                        atomicAdd(&g_pool[cur_b * C + c0 + 1], ph);
                        if (sl == 0) atomicAdd(&g_cnt[cur_b], (float)pcnt);
                    }
                    cur_b = b; pacc = pack2(0.f, 0.f); pcnt = 0;
                }
                u64 xv = *(const u64*)&xp[c0];
                pacc = fma2(xv, kONE, pacc);
                pcnt++;
            }
        }
        __syncwarp();
        // mask projection: lane = point
        if (lane < valid) {
            const float* mr = &SM[lane * YPITCH];
            u64 a0 = pack2(s_mb2, 0.f);
#pragma unroll
            for (int k = 0; k < 16; k++) {
                u64 y2 = *(const u64*)&mr[2 * k];
                u64 wv = *(const u64*)&s_mw2[2 * k];
                a0 = fma2(y2, wv, a0);
            }
            mask_out[base + lane] = sum2(a0);
        }
        __syncwarp();
    }

    if (cur_b >= 0) {
        float pl, ph;
        asm("mov.b64 {%0, %1}, %2;" : "=f"(pl), "=f"(ph) : "l"(pacc));
        atomicAdd(&g_pool[cur_b * C + c0],     pl);
        atomicAdd(&g_pool[cur_b * C + c0 + 1], ph);
        if (sl == 0) atomicAdd(&g_cnt[cur_b], (float)pcnt);
    }
    atomicAdd(&g_sumH[c0],      sumH0);
    atomicAdd(&g_sumH[c0 + 1],  sumH1);
    atomicAdd(&g_sumH2[c0],     sumH20);
    atomicAdd(&g_sumH2[c0 + 1], sumH21);
}

// ================= FINALIZE =================
__global__ void finalize_kernel(
    const float* __restrict__ w1, const float* __restrict__ b1,
    const float* __restrict__ gamma, const float* __restrict__ beta,
    const float* __restrict__ iou_w, const float* __restrict__ iou_b,
    float* __restrict__ out_pooled, float* __restrict__ out_iou,
    int n, int B)
{
    int t = threadIdx.x;  // channel
    float inv = 1.f / (float)n;
    float mu  = g_sumH[t] * inv;
    float var = g_sumH2[t] * inv - mu * mu;
    float s   = gamma[t] * rsqrtf(var + 1e-4f);
    g_b1f[t] = beta[t] + (b1[t] - mu) * s;
#pragma unroll
    for (int k = 0; k < C; k++) g_w1f[k * C + t] = w1[k * C + t] * s;

    float iw = iou_w[t];
    for (int b = 0; b < B; b++) {
        float cnt = fmaxf(g_cnt[b], 1.f);
        float pm  = g_pool[b * C + t] / cnt;
        out_pooled[b * C + t] = pm;
        float v = pm * iw;
#pragma unroll
        for (int o = 16; o > 0; o >>= 1) v += __shfl_xor_sync(0xffffffffu, v, o);
        if (t == 0) out_iou[b] = v + iou_b[0];
    }
}

// ================= PASS 2 =================
__global__ void __launch_bounds__(32 * WPB, 4) pass2_kernel(
    const float* __restrict__ feats,
    const float* __restrict__ w2, const float* __restrict__ ob2,
    float* __restrict__ off_out, int n, int tiles_total, int tpw)
{
    __shared__ float sx[WPB][32 * XPITCH];
    __shared__ float sy[WPB][32 * YPITCH];
    __shared__ float s_w2c[3][C];
    __shared__ float s_ob2[3];

    const int lane = threadIdx.x & 31;
    const int wi   = threadIdx.x >> 5;
    const int hw   = lane >> 4;
    const int sl   = lane & 15;
    const int c0   = 2 * sl;

    if (threadIdx.x < C) {
        s_w2c[0][threadIdx.x] = w2[threadIdx.x * 3 + 0];
        s_w2c[1][threadIdx.x] = w2[threadIdx.x * 3 + 1];
        s_w2c[2][threadIdx.x] = w2[threadIdx.x * 3 + 2];
    }
    if (threadIdx.x < 3) s_ob2[threadIdx.x] = ob2[threadIdx.x];
    __syncthreads();

    u64 wp0[16], wp1[16];
#pragma unroll
    for (int kk = 0; kk < 16; kk++) {
        wp0[kk] = pack2(g_w1f[(2 * kk) * C + c0],     g_w1f[(2 * kk + 1) * C + c0]);
        wp1[kk] = pack2(g_w1f[(2 * kk) * C + c0 + 1], g_w1f[(2 * kk + 1) * C + c0 + 1]);
    }
    const float b10 = g_b1f[c0], b11 = g_b1f[c0 + 1];

    const int gwid = blockIdx.x * WPB + wi;
    int t0 = gwid * tpw;
    int t1 = t0 + tpw; if (t1 > tiles_total) t1 = tiles_total;

    float* SX = sx[wi];
    float* SY = sy[wi];

    for (int tile = t0; tile < t1; tile++) {
        const int base = tile * 32;
        int valid = n - base; if (valid > 32) valid = 32;
        const int lim = valid * 8;
        const float4* src = (const float4*)(feats + (size_t)base * C);
#pragma unroll
        for (int j = 0; j < 8; j++) {
            int L = lane + 32 * j;
            float4 v = make_float4(0.f, 0.f, 0.f, 0.f);
            if (L < lim) v = src[L];
            *(float4*)&SX[(L >> 3) * XPITCH + 4 * (L & 7)] = v;
        }
        __syncwarp();

#pragma unroll 2
        for (int i = 0; i < 16; i++) {
            const int p = 2 * i + hw;
            if (p < valid) {
                const float* xp = &SX[p * XPITCH];
                u64 h0a = pack2(b10, 0.f), h0b = pack2(0.f, 0.f);
                u64 h1a = pack2(b11, 0.f), h1b = pack2(0.f, 0.f);
#pragma unroll
                for (int j = 0; j < 8; j++) {
                    ulonglong2 q = *(const ulonglong2*)&xp[4 * j];
                    h0a = fma2(q.x, wp0[2 * j],     h0a);
                    h0b = fma2(q.y, wp0[2 * j + 1], h0b);
                    h1a = fma2(q.x, wp1[2 * j],     h1a);
                    h1b = fma2(q.y, wp1[2 * j + 1], h1b);
                }
                float h0 = fmaxf(sum2(h0a) + sum2(h0b), 0.f);
                float h1 = fmaxf(sum2(h1a) + sum2(h1b), 0.f);
                *(u64*)&SY[p * YPITCH + c0] = pack2(h0, h1);
            }
        }
        __syncwarp();

        if (lane < valid) {
            const float* yr = &SY[lane * YPITCH];
            u64 a0 = pack2(s_ob2[0], 0.f);
            u64 a1 = pack2(s_ob2[1], 0.f);
            u64 a2 = pack2(s_ob2[2], 0.f);
#pragma unroll
            for (int k = 0; k < 16; k++) {
                u64 y2 = *(const u64*)&yr[2 * k];
                a0 = fma2(y2, *(const u64*)&s_w2c[0][2 * k], a0);
                a1 = fma2(y2, *(const u64*)&s_w2c[1][2 * k], a1);
                a2 = fma2(y2, *(const u64*)&s_w2c[2][2 * k], a2);
            }
            size_t o = (size_t)(base + lane) * 3;
            off_out[o + 0] = sum2(a0);
            off_out[o + 1] = sum2(a1);
            off_out[o + 2] = sum2(a2);
        }
        __syncwarp();
    }
}

// ================= LAUNCH =================
extern "C" void kernel_launch(void* const* d_in, const int* in_sizes, int n_in,
                              void* d_out, int out_size) {
    const float* feats = (const float*)d_in[0];
    const int*   bidx  = (const int*)  d_in[1];
    const float* w1    = (const float*)d_in[2];
    const float* b1    = (const float*)d_in[3];
    const float* gamma = (const float*)d_in[4];
    const float* beta  = (const float*)d_in[5];
    const float* w2    = (const float*)d_in[6];
    const float* ob2   = (const float*)d_in[7];
    const float* mw1   = (const float*)d_in[8];
    const float* mb1   = (const float*)d_in[9];
    const float* mw2   = (const float*)d_in[10];
    const float* mb2   = (const float*)d_in[11];
    const float* iw    = (const float*)d_in[12];
    const float* ib    = (const float*)d_in[13];

    int n = in_sizes[1];
    int B = (out_size - 4 * n) / 33;
    if (B < 1) B = 1;
    if (B > 64) B = 64;

    float* out        = (float*)d_out;
    float* out_off    = out;
    float* out_mask   = out + (size_t)3 * n;
    float* out_pooled = out + (size_t)4 * n;
    float* out_iou    = out_pooled + (size_t)B * C;

    int tiles  = (n + 31) / 32;
    int blocks = 608;
    int warps  = blocks * WPB;
    int tpw    = (tiles + warps - 1) / warps;

    zero_kernel<<<1, 1024>>>(B);
    pass1_kernel<<<blocks, 32 * WPB>>>(feats, bidx, w1, b1, mw1, mb1, mw2, mb2,
                                       out_mask, n, tiles, tpw);
    finalize_kernel<<<1, 32>>>(w1, b1, gamma, beta, iw, ib,
                               out_pooled, out_iou, n, B);
    pass2_kernel<<<blocks, 32 * WPB>>>(feats, w2, ob2, out_off, n, tiles, tpw);
}

// round 4
// speedup vs baseline: 1.3297x; 1.2216x over previous
#include <cuda_runtime.h>

// InstHead fused. R4: tensor-core tf32 GEMMs (mma.sync m16n8k8, 3xTF32 split)
// for both 32x32 layers. BN stats & pooled sums folded into pass1; BN folded
// into W1 for pass2.

#define C 32
#define WPB 4
typedef unsigned int u32;

__device__ __forceinline__ u32 f2tf(float x) {
    u32 r; asm("cvt.rna.tf32.f32 %0, %1;" : "=r"(r) : "f"(x)); return r;
}
__device__ __forceinline__ void split_tf(float x, u32& hi, u32& lo) {
    hi = f2tf(x);
    lo = f2tf(x - __uint_as_float(hi));
}

#define MMA(d0,d1,d2,d3,a0,a1,a2,a3,b0,b1) \
    asm("mma.sync.aligned.m16n8k8.row.col.f32.tf32.tf32.f32 " \
        "{%0,%1,%2,%3}, {%4,%5,%6,%7}, {%8,%9}, {%0,%1,%2,%3};" \
        : "+f"(d0), "+f"(d1), "+f"(d2), "+f"(d3) \
        : "r"(a0), "r"(a1), "r"(a2), "r"(a3), "r"(b0), "r"(b1))

// ---- scratch ----
__device__ float g_pool[64 * C];
__device__ float g_cnt[64];
__device__ float g_sumH[C];
__device__ float g_sumH2[C];
__device__ float g_w1f[C * C];
__device__ float g_b1f[C];

__global__ void zero_kernel(int B) {
    int t = threadIdx.x;
    for (int i = t; i < B * C; i += blockDim.x) g_pool[i] = 0.f;
    if (t < B) g_cnt[t] = 0.f;
    if (t < C) { g_sumH[t] = 0.f; g_sumH2[t] = 0.f; }
}

#define XP 36   // floats per point row; 144B (16B aligned), conflict-free frags

// ch(i) for lane: channel of accumulator slot i (i=0..7)
#define CH(i, tg) (((i) >> 1) * 8 + 2 * (tg) + ((i) & 1))

// ================= PASS 1 =================
__global__ void __launch_bounds__(32 * WPB, 2) pass1_kernel(
    const float* __restrict__ feats, const int* __restrict__ bidx,
    const float* __restrict__ w1,  const float* __restrict__ b1,
    const float* __restrict__ mw1, const float* __restrict__ mb1,
    const float* __restrict__ mw2, const float* __restrict__ mb2,
    float* __restrict__ mask_out, int n, int tiles_total, int tpw)
{
    __shared__ float sx[WPB][16 * XP];
    __shared__ int   sb[WPB][16];

    const int lane = threadIdx.x & 31;
    const int wi   = threadIdx.x >> 5;
    const int tg   = lane & 3;     // thread-in-group (col group)
    const int grp  = lane >> 2;    // row group 0..7

    // --- weight fragments (3xTF32 split), both GEMMs ---
    u32 Wh[4][4][2], Wl[4][4][2], Mh[4][4][2], Ml[4][4][2];
#pragma unroll
    for (int kb = 0; kb < 4; kb++)
#pragma unroll
        for (int nb = 0; nb < 4; nb++) {
            int r0 = kb * 8 + tg, col = nb * 8 + grp;
            split_tf(w1[r0 * C + col],        Wh[kb][nb][0], Wl[kb][nb][0]);
            split_tf(w1[(r0 + 4) * C + col],  Wh[kb][nb][1], Wl[kb][nb][1]);
            split_tf(mw1[r0 * C + col],       Mh[kb][nb][0], Ml[kb][nb][0]);
            split_tf(mw1[(r0 + 4) * C + col], Mh[kb][nb][1], Ml[kb][nb][1]);
        }
    float hb[8], mb[8], mwv[8];
#pragma unroll
    for (int i = 0; i < 8; i++) {
        int ch = CH(i, tg);
        hb[i]  = b1[ch];
        mb[i]  = mb1[ch];
        mwv[i] = mw2[ch];
    }
    const float mb2v = mb2[0];

    float s[8], s2[8];
#pragma unroll
    for (int i = 0; i < 8; i++) { s[i] = 0.f; s2[i] = 0.f; }

    float pacc = 0.f;   // pooled: lane = channel
    int   pcnt = 0, cur_b = -1;

    const int gwid = blockIdx.x * WPB + wi;
    int t0 = gwid * tpw;
    int t1 = t0 + tpw; if (t1 > tiles_total) t1 = tiles_total;

    float* SX = sx[wi];
    int*   SB = sb[wi];

    for (int tile = t0; tile < t1; tile++) {
        const int base = tile * 16;
        int valid = n - base; if (valid > 16) valid = 16;
        const int lim = valid * 8;          // float4 count
        const float4* src = (const float4*)(feats + (size_t)base * C);
#pragma unroll
        for (int j = 0; j < 4; j++) {
            int L = lane + 32 * j;
            float4 v = make_float4(0.f, 0.f, 0.f, 0.f);
            if (L < lim) v = src[L];
            *(float4*)&SX[(L >> 3) * XP + 4 * (L & 7)] = v;
        }
        if (lane < valid) SB[lane] = bidx[base + lane];
        __syncwarp();

        // --- A fragments + split ---
        u32 ah[4][4], al[4][4];
#pragma unroll
        for (int kb = 0; kb < 4; kb++) {
            float a0 = SX[grp * XP + kb * 8 + tg];
            float a1 = SX[(grp + 8) * XP + kb * 8 + tg];
            float a2 = SX[grp * XP + kb * 8 + tg + 4];
            float a3 = SX[(grp + 8) * XP + kb * 8 + tg + 4];
            split_tf(a0, ah[kb][0], al[kb][0]);
            split_tf(a1, ah[kb][1], al[kb][1]);
            split_tf(a2, ah[kb][2], al[kb][2]);
            split_tf(a3, ah[kb][3], al[kb][3]);
        }

        const bool full = (valid == 16);

        // --- h GEMM + stats ---
#pragma unroll
        for (int nb = 0; nb < 4; nb++) {
            float d0 = hb[2 * nb], d1 = hb[2 * nb + 1];
            float d2 = hb[2 * nb], d3 = hb[2 * nb + 1];
#pragma unroll
            for (int kb = 0; kb < 4; kb++) {
                MMA(d0, d1, d2, d3, ah[kb][0], ah[kb][1], ah[kb][2], ah[kb][3],
                    Wl[kb][nb][0], Wl[kb][nb][1]);
                MMA(d0, d1, d2, d3, al[kb][0], al[kb][1], al[kb][2], al[kb][3],
                    Wh[kb][nb][0], Wh[kb][nb][1]);
                MMA(d0, d1, d2, d3, ah[kb][0], ah[kb][1], ah[kb][2], ah[kb][3],
                    Wh[kb][nb][0], Wh[kb][nb][1]);
            }
            if (full) {
                s[2 * nb]      += d0 + d2;
                s2[2 * nb]     = fmaf(d0, d0, fmaf(d2, d2, s2[2 * nb]));
                s[2 * nb + 1]  += d1 + d3;
                s2[2 * nb + 1] = fmaf(d1, d1, fmaf(d3, d3, s2[2 * nb + 1]));
            } else {
                if (base + grp < n) {
                    s[2 * nb] += d0;          s2[2 * nb]     = fmaf(d0, d0, s2[2 * nb]);
                    s[2 * nb + 1] += d1;      s2[2 * nb + 1] = fmaf(d1, d1, s2[2 * nb + 1]);
                }
                if (base + grp + 8 < n) {
                    s[2 * nb] += d2;          s2[2 * nb]     = fmaf(d2, d2, s2[2 * nb]);
                    s[2 * nb + 1] += d3;      s2[2 * nb + 1] = fmaf(d3, d3, s2[2 * nb + 1]);
                }
            }
        }

        // --- mask GEMM + projection ---
        float p0 = 0.f, p1 = 0.f;   // rows grp, grp+8 partial dots
#pragma unroll
        for (int nb = 0; nb < 4; nb++) {
            float d0 = mb[2 * nb], d1 = mb[2 * nb + 1];
            float d2 = mb[2 * nb], d3 = mb[2 * nb + 1];
#pragma unroll
            for (int kb = 0; kb < 4; kb++) {
                MMA(d0, d1, d2, d3, ah[kb][0], ah[kb][1], ah[kb][2], ah[kb][3],
                    Ml[kb][nb][0], Ml[kb][nb][1]);
                MMA(d0, d1, d2, d3, al[kb][0], al[kb][1], al[kb][2], al[kb][3],
                    Mh[kb][nb][0], Mh[kb][nb][1]);
                MMA(d0, d1, d2, d3, ah[kb][0], ah[kb][1], ah[kb][2], ah[kb][3],
                    Mh[kb][nb][0], Mh[kb][nb][1]);
            }
            p0 = fmaf(fmaxf(d0, 0.f), mwv[2 * nb],
                 fmaf(fmaxf(d1, 0.f), mwv[2 * nb + 1], p0));
            p1 = fmaf(fmaxf(d2, 0.f), mwv[2 * nb],
                 fmaf(fmaxf(d3, 0.f), mwv[2 * nb + 1], p1));
        }
        p0 += __shfl_xor_sync(0xffffffffu, p0, 1);
        p0 += __shfl_xor_sync(0xffffffffu, p0, 2);
        p1 += __shfl_xor_sync(0xffffffffu, p1, 1);
        p1 += __shfl_xor_sync(0xffffffffu, p1, 2);
        if (tg == 0) {
            if (grp < valid)     mask_out[base + grp]     = p0 + mb2v;
            if (grp + 8 < valid) mask_out[base + grp + 8] = p1 + mb2v;
        }

        // --- pooled (lane = channel) ---
        if (full && SB[0] == SB[15]) {
            int b = SB[0];
            if (b != cur_b) {
                if (cur_b >= 0) {
                    atomicAdd(&g_pool[cur_b * C + lane], pacc);
                    if (lane == 0) atomicAdd(&g_cnt[cur_b], (float)pcnt);
                }
                cur_b = b; pacc = 0.f; pcnt = 0;
            }
            float a = 0.f;
#pragma unroll
            for (int p = 0; p < 16; p++) a += SX[p * XP + lane];
            pacc += a; pcnt += 16;
        } else {
            for (int p = 0; p < valid; p++) {
                int b = SB[p];
                if (b != cur_b) {
                    if (cur_b >= 0) {
                        atomicAdd(&g_pool[cur_b * C + lane], pacc);
                        if (lane == 0) atomicAdd(&g_cnt[cur_b], (float)pcnt);
                    }
                    cur_b = b; pacc = 0.f; pcnt = 0;
                }
                pacc += SX[p * XP + lane];
                pcnt++;
            }
        }
        __syncwarp();
    }

    if (cur_b >= 0) {
        atomicAdd(&g_pool[cur_b * C + lane], pacc);
        if (lane == 0) atomicAdd(&g_cnt[cur_b], (float)pcnt);
    }
    // reduce stats across row-groups (lanes sharing tg)
#pragma unroll
    for (int i = 0; i < 8; i++) {
#pragma unroll
        for (int o = 4; o < 32; o <<= 1) {
            s[i]  += __shfl_xor_sync(0xffffffffu, s[i],  o);
            s2[i] += __shfl_xor_sync(0xffffffffu, s2[i], o);
        }
    }
    if (grp == 0) {
#pragma unroll
        for (int i = 0; i < 8; i++) {
            int ch = CH(i, tg);
            atomicAdd(&g_sumH[ch],  s[i]);
            atomicAdd(&g_sumH2[ch], s2[i]);
        }
    }
}

// ================= FINALIZE =================
__global__ void finalize_kernel(
    const float* __restrict__ w1, const float* __restrict__ b1,
    const float* __restrict__ gamma, const float* __restrict__ beta,
    const float* __restrict__ iou_w, const float* __restrict__ iou_b,
    float* __restrict__ out_pooled, float* __restrict__ out_iou,
    int n, int B)
{
    int t = threadIdx.x;  // channel
    float inv = 1.f / (float)n;
    float mu  = g_sumH[t] * inv;
    float var = g_sumH2[t] * inv - mu * mu;
    float sc  = gamma[t] * rsqrtf(var + 1e-4f);
    g_b1f[t] = beta[t] + (b1[t] - mu) * sc;
#pragma unroll
    for (int k = 0; k < C; k++) g_w1f[k * C + t] = w1[k * C + t] * sc;

    float iw = iou_w[t];
    for (int b = 0; b < B; b++) {
        float cnt = fmaxf(g_cnt[b], 1.f);
        float pm  = g_pool[b * C + t] / cnt;
        out_pooled[b * C + t] = pm;
        float v = pm * iw;
#pragma unroll
        for (int o = 16; o > 0; o >>= 1) v += __shfl_xor_sync(0xffffffffu, v, o);
        if (t == 0) out_iou[b] = v + iou_b[0];
    }
}

// ================= PASS 2 =================
__global__ void __launch_bounds__(32 * WPB, 2) pass2_kernel(
    const float* __restrict__ feats,
    const float* __restrict__ w2, const float* __restrict__ ob2,
    float* __restrict__ off_out, int n, int tiles_total, int tpw)
{
    __shared__ float sx[WPB][16 * XP];

    const int lane = threadIdx.x & 31;
    const int wi   = threadIdx.x >> 5;
    const int tg   = lane & 3;
    const int grp  = lane >> 2;

    u32 Wh[4][4][2], Wl[4][4][2];
#pragma unroll
    for (int kb = 0; kb < 4; kb++)
#pragma unroll
        for (int nb = 0; nb < 4; nb++) {
            int r0 = kb * 8 + tg, col = nb * 8 + grp;
            split_tf(g_w1f[r0 * C + col],       Wh[kb][nb][0], Wl[kb][nb][0]);
            split_tf(g_w1f[(r0 + 4) * C + col], Wh[kb][nb][1], Wl[kb][nb][1]);
        }
    float fb[8], w2v0[8], w2v1[8], w2v2[8];
#pragma unroll
    for (int i = 0; i < 8; i++) {
        int ch = CH(i, tg);
        fb[i]   = g_b1f[ch];
        w2v0[i] = w2[ch * 3 + 0];
        w2v1[i] = w2[ch * 3 + 1];
        w2v2[i] = w2[ch * 3 + 2];
    }
    const float c0 = ob2[0], c1 = ob2[1], c2 = ob2[2];

    const int gwid = blockIdx.x * WPB + wi;
    int t0 = gwid * tpw;
    int t1 = t0 + tpw; if (t1 > tiles_total) t1 = tiles_total;

    float* SX = sx[wi];

    for (int tile = t0; tile < t1; tile++) {
        const int base = tile * 16;
        int valid = n - base; if (valid > 16) valid = 16;
        const int lim = valid * 8;
        const float4* src = (const float4*)(feats + (size_t)base * C);
#pragma unroll
        for (int j = 0; j < 4; j++) {
            int L = lane + 32 * j;
            float4 v = make_float4(0.f, 0.f, 0.f, 0.f);
            if (L < lim) v = src[L];
            *(float4*)&SX[(L >> 3) * XP + 4 * (L & 7)] = v;
        }
        __syncwarp();

        u32 ah[4][4], al[4][4];
#pragma unroll
        for (int kb = 0; kb < 4; kb++) {
            float a0 = SX[grp * XP + kb * 8 + tg];
            float a1 = SX[(grp + 8) * XP + kb * 8 + tg];
            float a2 = SX[grp * XP + kb * 8 + tg + 4];
            float a3 = SX[(grp + 8) * XP + kb * 8 + tg + 4];
            split_tf(a0, ah[kb][0], al[kb][0]);
            split_tf(a1, ah[kb][1], al[kb][1]);
            split_tf(a2, ah[kb][2], al[kb][2]);
            split_tf(a3, ah[kb][3], al[kb][3]);
        }

        float o00 = 0.f, o01 = 0.f, o02 = 0.f;   // row grp
        float o10 = 0.f, o11 = 0.f, o12 = 0.f;   // row grp+8
#pragma unroll
        for (int nb = 0; nb < 4; nb++) {
            float d0 = fb[2 * nb], d1 = fb[2 * nb + 1];
            float d2 = fb[2 * nb], d3 = fb[2 * nb + 1];
#pragma unroll
            for (int kb = 0; kb < 4; kb++) {
                MMA(d0, d1, d2, d3, ah[kb][0], ah[kb][1], ah[kb][2], ah[kb][3],
                    Wl[kb][nb][0], Wl[kb][nb][1]);
                MMA(d0, d1, d2, d3, al[kb][0], al[kb][1], al[kb][2], al[kb][3],
                    Wh[kb][nb][0], Wh[kb][nb][1]);
                MMA(d0, d1, d2, d3, ah[kb][0], ah[kb][1], ah[kb][2], ah[kb][3],
                    Wh[kb][nb][0], Wh[kb][nb][1]);
            }
            d0 = fmaxf(d0, 0.f); d1 = fmaxf(d1, 0.f);
            d2 = fmaxf(d2, 0.f); d3 = fmaxf(d3, 0.f);
            o00 = fmaf(d0, w2v0[2 * nb], fmaf(d1, w2v0[2 * nb + 1], o00));
            o01 = fmaf(d0, w2v1[2 * nb], fmaf(d1, w2v1[2 * nb + 1], o01));
            o02 = fmaf(d0, w2v2[2 * nb], fmaf(d1, w2v2[2 * nb + 1], o02));
            o10 = fmaf(d2, w2v0[2 * nb], fmaf(d3, w2v0[2 * nb + 1], o10));
            o11 = fmaf(d2, w2v1[2 * nb], fmaf(d3, w2v1[2 * nb + 1], o11));
            o12 = fmaf(d2, w2v2[2 * nb], fmaf(d3, w2v2[2 * nb + 1], o12));
        }
#pragma unroll
        for (int o = 1; o <= 2; o <<= 1) {
            o00 += __shfl_xor_sync(0xffffffffu, o00, o);
            o01 += __shfl_xor_sync(0xffffffffu, o01, o);
            o02 += __shfl_xor_sync(0xffffffffu, o02, o);
            o10 += __shfl_xor_sync(0xffffffffu, o10, o);
            o11 += __shfl_xor_sync(0xffffffffu, o11, o);
            o12 += __shfl_xor_sync(0xffffffffu, o12, o);
        }
        if (tg == 0) {
            if (grp < valid) {
                size_t o = (size_t)(base + grp) * 3;
                off_out[o + 0] = o00 + c0;
                off_out[o + 1] = o01 + c1;
                off_out[o + 2] = o02 + c2;
            }
            if (grp + 8 < valid) {
                size_t o = (size_t)(base + grp + 8) * 3;
                off_out[o + 0] = o10 + c0;
                off_out[o + 1] = o11 + c1;
                off_out[o + 2] = o12 + c2;
            }
        }
        __syncwarp();
    }
}

// ================= LAUNCH =================
extern "C" void kernel_launch(void* const* d_in, const int* in_sizes, int n_in,
                              void* d_out, int out_size) {
    const float* feats = (const float*)d_in[0];
    const int*   bidx  = (const int*)  d_in[1];
    const float* w1    = (const float*)d_in[2];
    const float* b1    = (const float*)d_in[3];
    const float* gamma = (const float*)d_in[4];
    const float* beta  = (const float*)d_in[5];
    const float* w2    = (const float*)d_in[6];
    const float* ob2   = (const float*)d_in[7];
    const float* mw1   = (const float*)d_in[8];
    const float* mb1   = (const float*)d_in[9];
    const float* mw2   = (const float*)d_in[10];
    const float* mb2   = (const float*)d_in[11];
    const float* iw    = (const float*)d_in[12];
    const float* ib    = (const float*)d_in[13];

    int n = in_sizes[1];
    int B = (out_size - 4 * n) / 33;
    if (B < 1) B = 1;
    if (B > 64) B = 64;

    float* out        = (float*)d_out;
    float* out_off    = out;
    float* out_mask   = out + (size_t)3 * n;
    float* out_pooled = out + (size_t)4 * n;
    float* out_iou    = out_pooled + (size_t)B * C;

    int tiles  = (n + 15) / 16;
    int blocks = 608;
    int warps  = blocks * WPB;
    int tpw    = (tiles + warps - 1) / warps;

    zero_kernel<<<1, 1024>>>(B);
    pass1_kernel<<<blocks, 32 * WPB>>>(feats, bidx, w1, b1, mw1, mb1, mw2, mb2,
                                       out_mask, n, tiles, tpw);
    finalize_kernel<<<1, 32>>>(w1, b1, gamma, beta, iw, ib,
                               out_pooled, out_iou, n, B);
    pass2_kernel<<<blocks, 32 * WPB>>>(feats, w2, ob2, out_off, n, tiles, tpw);
}

// round 5
// speedup vs baseline: 1.7318x; 1.3024x over previous
#include <cuda_runtime.h>

// InstHead fused. R5: 32-point tiles (2x m16 frags -> 8 indep MMA chains),
// mask GEMM uses 2-term TF32 split, pass2 capped for 3 CTAs/SM.

#define C 32
#define WPB 4
typedef unsigned int u32;

__device__ __forceinline__ u32 f2tf(float x) {
    u32 r; asm("cvt.rna.tf32.f32 %0, %1;" : "=r"(r) : "f"(x)); return r;
}
__device__ __forceinline__ void split_tf(float x, u32& hi, u32& lo) {
    hi = f2tf(x);
    lo = f2tf(x - __uint_as_float(hi));
}

#define MMA(d0,d1,d2,d3,a0,a1,a2,a3,b0,b1) \
    asm("mma.sync.aligned.m16n8k8.row.col.f32.tf32.tf32.f32 " \
        "{%0,%1,%2,%3}, {%4,%5,%6,%7}, {%8,%9}, {%0,%1,%2,%3};" \
        : "+f"(d0), "+f"(d1), "+f"(d2), "+f"(d3) \
        : "r"(a0), "r"(a1), "r"(a2), "r"(a3), "r"(b0), "r"(b1))

// ---- scratch ----
__device__ float g_pool[64 * C];
__device__ float g_cnt[64];
__device__ float g_sumH[C];
__device__ float g_sumH2[C];
__device__ float g_w1f[C * C];
__device__ float g_b1f[C];

__global__ void zero_kernel(int B) {
    int t = threadIdx.x;
    for (int i = t; i < B * C; i += blockDim.x) g_pool[i] = 0.f;
    if (t < B) g_cnt[t] = 0.f;
    if (t < C) { g_sumH[t] = 0.f; g_sumH2[t] = 0.f; }
}

#define XP 36
#define TP 32   // points per tile
#define CH(i, tg) (((i) >> 1) * 8 + 2 * (tg) + ((i) & 1))

// ================= PASS 1 =================
__global__ void __launch_bounds__(32 * WPB, 2) pass1_kernel(
    const float* __restrict__ feats, const int* __restrict__ bidx,
    const float* __restrict__ w1,  const float* __restrict__ b1,
    const float* __restrict__ mw1, const float* __restrict__ mb1,
    const float* __restrict__ mw2, const float* __restrict__ mb2,
    float* __restrict__ mask_out, int n, int tiles_total, int tpw)
{
    __shared__ float sx[WPB][TP * XP];
    __shared__ int   sb[WPB][TP];

    const int lane = threadIdx.x & 31;
    const int wi   = threadIdx.x >> 5;
    const int tg   = lane & 3;
    const int grp  = lane >> 2;

    // weights: h GEMM 3-term (Wh+Wl), mask GEMM 2-term (Mh only)
    u32 Wh[4][4][2], Wl[4][4][2], Mh[4][4][2];
#pragma unroll
    for (int kb = 0; kb < 4; kb++)
#pragma unroll
        for (int nb = 0; nb < 4; nb++) {
            int r0 = kb * 8 + tg, col = nb * 8 + grp;
            split_tf(w1[r0 * C + col],       Wh[kb][nb][0], Wl[kb][nb][0]);
            split_tf(w1[(r0 + 4) * C + col], Wh[kb][nb][1], Wl[kb][nb][1]);
            Mh[kb][nb][0] = f2tf(mw1[r0 * C + col]);
            Mh[kb][nb][1] = f2tf(mw1[(r0 + 4) * C + col]);
        }
    float hb[8], mbv[8], mwv[8];
#pragma unroll
    for (int i = 0; i < 8; i++) {
        int ch = CH(i, tg);
        hb[i]  = b1[ch];
        mbv[i] = mb1[ch];
        mwv[i] = mw2[ch];
    }
    const float mb2v = mb2[0];

    float s[8], s2[8];
#pragma unroll
    for (int i = 0; i < 8; i++) { s[i] = 0.f; s2[i] = 0.f; }

    float pacc = 0.f;
    int   pcnt = 0, cur_b = -1;

    const int gwid = blockIdx.x * WPB + wi;
    int t0 = gwid * tpw;
    int t1 = t0 + tpw; if (t1 > tiles_total) t1 = tiles_total;

    float* SX = sx[wi];
    int*   SB = sb[wi];

    for (int tile = t0; tile < t1; tile++) {
        const int base = tile * TP;
        int valid = n - base; if (valid > TP) valid = TP;
        const int lim = valid * 8;
        const float4* src = (const float4*)(feats + (size_t)base * C);
#pragma unroll
        for (int j = 0; j < 8; j++) {
            int L = lane + 32 * j;
            float4 v = make_float4(0.f, 0.f, 0.f, 0.f);
            if (L < lim) v = src[L];
            *(float4*)&SX[(L >> 3) * XP + 4 * (L & 7)] = v;
        }
        if (lane < valid) SB[lane] = bidx[base + lane];
        __syncwarp();

        u32 ah[2][4][4], al[2][4][4];
#pragma unroll
        for (int m = 0; m < 2; m++)
#pragma unroll
            for (int kb = 0; kb < 4; kb++) {
                int r = m * 16 + grp;
                split_tf(SX[r * XP + kb * 8 + tg],           ah[m][kb][0], al[m][kb][0]);
                split_tf(SX[(r + 8) * XP + kb * 8 + tg],     ah[m][kb][1], al[m][kb][1]);
                split_tf(SX[r * XP + kb * 8 + tg + 4],       ah[m][kb][2], al[m][kb][2]);
                split_tf(SX[(r + 8) * XP + kb * 8 + tg + 4], ah[m][kb][3], al[m][kb][3]);
            }

        const bool full = (valid == TP);

        // --- h GEMM + stats ---
#pragma unroll
        for (int nb = 0; nb < 4; nb++) {
            float d[2][4];
#pragma unroll
            for (int m = 0; m < 2; m++) {
                d[m][0] = hb[2 * nb]; d[m][1] = hb[2 * nb + 1];
                d[m][2] = hb[2 * nb]; d[m][3] = hb[2 * nb + 1];
            }
#pragma unroll
            for (int kb = 0; kb < 4; kb++)
#pragma unroll
                for (int m = 0; m < 2; m++) {
                    MMA(d[m][0], d[m][1], d[m][2], d[m][3],
                        ah[m][kb][0], ah[m][kb][1], ah[m][kb][2], ah[m][kb][3],
                        Wl[kb][nb][0], Wl[kb][nb][1]);
                    MMA(d[m][0], d[m][1], d[m][2], d[m][3],
                        al[m][kb][0], al[m][kb][1], al[m][kb][2], al[m][kb][3],
                        Wh[kb][nb][0], Wh[kb][nb][1]);
                    MMA(d[m][0], d[m][1], d[m][2], d[m][3],
                        ah[m][kb][0], ah[m][kb][1], ah[m][kb][2], ah[m][kb][3],
                        Wh[kb][nb][0], Wh[kb][nb][1]);
                }
            if (full) {
#pragma unroll
                for (int m = 0; m < 2; m++) {
                    s[2 * nb]      += d[m][0] + d[m][2];
                    s2[2 * nb]      = fmaf(d[m][0], d[m][0], fmaf(d[m][2], d[m][2], s2[2 * nb]));
                    s[2 * nb + 1]  += d[m][1] + d[m][3];
                    s2[2 * nb + 1]  = fmaf(d[m][1], d[m][1], fmaf(d[m][3], d[m][3], s2[2 * nb + 1]));
                }
            } else {
#pragma unroll
                for (int m = 0; m < 2; m++) {
                    if (base + m * 16 + grp < n) {
                        s[2 * nb] += d[m][0];     s2[2 * nb]     = fmaf(d[m][0], d[m][0], s2[2 * nb]);
                        s[2 * nb + 1] += d[m][1]; s2[2 * nb + 1] = fmaf(d[m][1], d[m][1], s2[2 * nb + 1]);
                    }
                    if (base + m * 16 + grp + 8 < n) {
                        s[2 * nb] += d[m][2];     s2[2 * nb]     = fmaf(d[m][2], d[m][2], s2[2 * nb]);
                        s[2 * nb + 1] += d[m][3]; s2[2 * nb + 1] = fmaf(d[m][3], d[m][3], s2[2 * nb + 1]);
                    }
                }
            }
        }

        // --- mask GEMM (2-term) + projection ---
        float p[2][2] = {{0.f, 0.f}, {0.f, 0.f}};
#pragma unroll
        for (int nb = 0; nb < 4; nb++) {
            float d[2][4];
#pragma unroll
            for (int m = 0; m < 2; m++) {
                d[m][0] = mbv[2 * nb]; d[m][1] = mbv[2 * nb + 1];
                d[m][2] = mbv[2 * nb]; d[m][3] = mbv[2 * nb + 1];
            }
#pragma unroll
            for (int kb = 0; kb < 4; kb++)
#pragma unroll
                for (int m = 0; m < 2; m++) {
                    MMA(d[m][0], d[m][1], d[m][2], d[m][3],
                        al[m][kb][0], al[m][kb][1], al[m][kb][2], al[m][kb][3],
                        Mh[kb][nb][0], Mh[kb][nb][1]);
                    MMA(d[m][0], d[m][1], d[m][2], d[m][3],
                        ah[m][kb][0], ah[m][kb][1], ah[m][kb][2], ah[m][kb][3],
                        Mh[kb][nb][0], Mh[kb][nb][1]);
                }
#pragma unroll
            for (int m = 0; m < 2; m++) {
                p[m][0] = fmaf(fmaxf(d[m][0], 0.f), mwv[2 * nb],
                          fmaf(fmaxf(d[m][1], 0.f), mwv[2 * nb + 1], p[m][0]));
                p[m][1] = fmaf(fmaxf(d[m][2], 0.f), mwv[2 * nb],
                          fmaf(fmaxf(d[m][3], 0.f), mwv[2 * nb + 1], p[m][1]));
            }
        }
#pragma unroll
        for (int m = 0; m < 2; m++) {
            p[m][0] += __shfl_xor_sync(0xffffffffu, p[m][0], 1);
            p[m][0] += __shfl_xor_sync(0xffffffffu, p[m][0], 2);
            p[m][1] += __shfl_xor_sync(0xffffffffu, p[m][1], 1);
            p[m][1] += __shfl_xor_sync(0xffffffffu, p[m][1], 2);
        }
        if (tg == 0) {
#pragma unroll
            for (int m = 0; m < 2; m++) {
                int r = m * 16 + grp;
                if (r < valid)     mask_out[base + r]     = p[m][0] + mb2v;
                if (r + 8 < valid) mask_out[base + r + 8] = p[m][1] + mb2v;
            }
        }

        // --- pooled (lane = channel) ---
        if (full && SB[0] == SB[TP - 1]) {
            int b = SB[0];
            if (b != cur_b) {
                if (cur_b >= 0) {
                    atomicAdd(&g_pool[cur_b * C + lane], pacc);
                    if (lane == 0) atomicAdd(&g_cnt[cur_b], (float)pcnt);
                }
                cur_b = b; pacc = 0.f; pcnt = 0;
            }
            float a = 0.f;
#pragma unroll
            for (int pnt = 0; pnt < TP; pnt++) a += SX[pnt * XP + lane];
            pacc += a; pcnt += TP;
        } else {
            for (int pnt = 0; pnt < valid; pnt++) {
                int b = SB[pnt];
                if (b != cur_b) {
                    if (cur_b >= 0) {
                        atomicAdd(&g_pool[cur_b * C + lane], pacc);
                        if (lane == 0) atomicAdd(&g_cnt[cur_b], (float)pcnt);
                    }
                    cur_b = b; pacc = 0.f; pcnt = 0;
                }
                pacc += SX[pnt * XP + lane];
                pcnt++;
            }
        }
        __syncwarp();
    }

    if (cur_b >= 0) {
        atomicAdd(&g_pool[cur_b * C + lane], pacc);
        if (lane == 0) atomicAdd(&g_cnt[cur_b], (float)pcnt);
    }
#pragma unroll
    for (int i = 0; i < 8; i++) {
#pragma unroll
        for (int o = 4; o < 32; o <<= 1) {
            s[i]  += __shfl_xor_sync(0xffffffffu, s[i],  o);
            s2[i] += __shfl_xor_sync(0xffffffffu, s2[i], o);
        }
    }
    if (grp == 0) {
#pragma unroll
        for (int i = 0; i < 8; i++) {
            int ch = CH(i, tg);
            atomicAdd(&g_sumH[ch],  s[i]);
            atomicAdd(&g_sumH2[ch], s2[i]);
        }
    }
}

// ================= FINALIZE =================
__global__ void finalize_kernel(
    const float* __restrict__ w1, const float* __restrict__ b1,
    const float* __restrict__ gamma, const float* __restrict__ beta,
    const float* __restrict__ iou_w, const float* __restrict__ iou_b,
    float* __restrict__ out_pooled, float* __restrict__ out_iou,
    int n, int B)
{
    int t = threadIdx.x;
    float inv = 1.f / (float)n;
    float mu  = g_sumH[t] * inv;
    float var = g_sumH2[t] * inv - mu * mu;
    float sc  = gamma[t] * rsqrtf(var + 1e-4f);
    g_b1f[t] = beta[t] + (b1[t] - mu) * sc;
#pragma unroll
    for (int k = 0; k < C; k++) g_w1f[k * C + t] = w1[k * C + t] * sc;

    float iw = iou_w[t];
    for (int b = 0; b < B; b++) {
        float cnt = fmaxf(g_cnt[b], 1.f);
        float pm  = g_pool[b * C + t] / cnt;
        out_pooled[b * C + t] = pm;
        float v = pm * iw;
#pragma unroll
        for (int o = 16; o > 0; o >>= 1) v += __shfl_xor_sync(0xffffffffu, v, o);
        if (t == 0) out_iou[b] = v + iou_b[0];
    }
}

// ================= PASS 2 =================
__global__ void __launch_bounds__(32 * WPB, 3) pass2_kernel(
    const float* __restrict__ feats,
    const float* __restrict__ w2, const float* __restrict__ ob2,
    float* __restrict__ off_out, int n, int tiles_total, int tpw)
{
    __shared__ float sx[WPB][TP * XP];

    const int lane = threadIdx.x & 31;
    const int wi   = threadIdx.x >> 5;
    const int tg   = lane & 3;
    const int grp  = lane >> 2;

    u32 Wh[4][4][2], Wl[4][4][2];
#pragma unroll
    for (int kb = 0; kb < 4; kb++)
#pragma unroll
        for (int nb = 0; nb < 4; nb++) {
            int r0 = kb * 8 + tg, col = nb * 8 + grp;
            split_tf(g_w1f[r0 * C + col],       Wh[kb][nb][0], Wl[kb][nb][0]);
            split_tf(g_w1f[(r0 + 4) * C + col], Wh[kb][nb][1], Wl[kb][nb][1]);
        }
    float fb[8], w2v0[8], w2v1[8], w2v2[8];
#pragma unroll
    for (int i = 0; i < 8; i++) {
        int ch = CH(i, tg);
        fb[i]   = g_b1f[ch];
        w2v0[i] = w2[ch * 3 + 0];
        w2v1[i] = w2[ch * 3 + 1];
        w2v2[i] = w2[ch * 3 + 2];
    }
    const float c0 = ob2[0], c1 = ob2[1], c2 = ob2[2];

    const int gwid = blockIdx.x * WPB + wi;
    int t0 = gwid * tpw;
    int t1 = t0 + tpw; if (t1 > tiles_total) t1 = tiles_total;

    float* SX = sx[wi];

    for (int tile = t0; tile < t1; tile++) {
        const int base = tile * TP;
        int valid = n - base; if (valid > TP) valid = TP;
        const int lim = valid * 8;
        const float4* src = (const float4*)(feats + (size_t)base * C);
#pragma unroll
        for (int j = 0; j < 8; j++) {
            int L = lane + 32 * j;
            float4 v = make_float4(0.f, 0.f, 0.f, 0.f);
            if (L < lim) v = src[L];
            *(float4*)&SX[(L >> 3) * XP + 4 * (L & 7)] = v;
        }
        __syncwarp();

        u32 ah[2][4][4], al[2][4][4];
#pragma unroll
        for (int m = 0; m < 2; m++)
#pragma unroll
            for (int kb = 0; kb < 4; kb++) {
                int r = m * 16 + grp;
                split_tf(SX[r * XP + kb * 8 + tg],           ah[m][kb][0], al[m][kb][0]);
                split_tf(SX[(r + 8) * XP + kb * 8 + tg],     ah[m][kb][1], al[m][kb][1]);
                split_tf(SX[r * XP + kb * 8 + tg + 4],       ah[m][kb][2], al[m][kb][2]);
                split_tf(SX[(r + 8) * XP + kb * 8 + tg + 4], ah[m][kb][3], al[m][kb][3]);
            }

        float o0[2][2], o1[2][2], o2[2][2];
#pragma unroll
        for (int m = 0; m < 2; m++)
#pragma unroll
            for (int r = 0; r < 2; r++) { o0[m][r] = 0.f; o1[m][r] = 0.f; o2[m][r] = 0.f; }

#pragma unroll
        for (int nb = 0; nb < 4; nb++) {
            float d[2][4];
#pragma unroll
            for (int m = 0; m < 2; m++) {
                d[m][0] = fb[2 * nb]; d[m][1] = fb[2 * nb + 1];
                d[m][2] = fb[2 * nb]; d[m][3] = fb[2 * nb + 1];
            }
#pragma unroll
            for (int kb = 0; kb < 4; kb++)
#pragma unroll
                for (int m = 0; m < 2; m++) {
                    MMA(d[m][0], d[m][1], d[m][2], d[m][3],
                        ah[m][kb][0], ah[m][kb][1], ah[m][kb][2], ah[m][kb][3],
                        Wl[kb][nb][0], Wl[kb][nb][1]);
                    MMA(d[m][0], d[m][1], d[m][2], d[m][3],
                        al[m][kb][0], al[m][kb][1], al[m][kb][2], al[m][kb][3],
                        Wh[kb][nb][0], Wh[kb][nb][1]);
                    MMA(d[m][0], d[m][1], d[m][2], d[m][3],
                        ah[m][kb][0], ah[m][kb][1], ah[m][kb][2], ah[m][kb][3],
                        Wh[kb][nb][0], Wh[kb][nb][1]);
                }
#pragma unroll
            for (int m = 0; m < 2; m++) {
                float e0 = fmaxf(d[m][0], 0.f), e1 = fmaxf(d[m][1], 0.f);
                float e2 = fmaxf(d[m][2], 0.f), e3 = fmaxf(d[m][3], 0.f);
                o0[m][0] = fmaf(e0, w2v0[2 * nb], fmaf(e1, w2v0[2 * nb + 1], o0[m][0]));
                o1[m][0] = fmaf(e0, w2v1[2 * nb], fmaf(e1, w2v1[2 * nb + 1], o1[m][0]));
                o2[m][0] = fmaf(e0, w2v2[2 * nb], fmaf(e1, w2v2[2 * nb + 1], o2[m][0]));
                o0[m][1] = fmaf(e2, w2v0[2 * nb], fmaf(e3, w2v0[2 * nb + 1], o0[m][1]));
                o1[m][1] = fmaf(e2, w2v1[2 * nb], fmaf(e3, w2v1[2 * nb + 1], o1[m][1]));
                o2[m][1] = fmaf(e2, w2v2[2 * nb], fmaf(e3, w2v2[2 * nb + 1], o2[m][1]));
            }
        }
#pragma unroll
        for (int m = 0; m < 2; m++)
#pragma unroll
            for (int r = 0; r < 2; r++) {
#pragma unroll
                for (int o = 1; o <= 2; o <<= 1) {
                    o0[m][r] += __shfl_xor_sync(0xffffffffu, o0[m][r], o);
                    o1[m][r] += __shfl_xor_sync(0xffffffffu, o1[m][r], o);
                    o2[m][r] += __shfl_xor_sync(0xffffffffu, o2[m][r], o);
                }
            }
        if (tg == 0) {
#pragma unroll
            for (int m = 0; m < 2; m++) {
#pragma unroll
                for (int r = 0; r < 2; r++) {
                    int row = m * 16 + grp + r * 8;
                    if (row < valid) {
                        size_t o = (size_t)(base + row) * 3;
                        off_out[o + 0] = o0[m][r] + c0;
                        off_out[o + 1] = o1[m][r] + c1;
                        off_out[o + 2] = o2[m][r] + c2;
                    }
                }
            }
        }
        __syncwarp();
    }
}

// ================= LAUNCH =================
extern "C" void kernel_launch(void* const* d_in, const int* in_sizes, int n_in,
                              void* d_out, int out_size) {
    const float* feats = (const float*)d_in[0];
    const int*   bidx  = (const int*)  d_in[1];
    const float* w1    = (const float*)d_in[2];
    const float* b1    = (const float*)d_in[3];
    const float* gamma = (const float*)d_in[4];
    const float* beta  = (const float*)d_in[5];
    const float* w2    = (const float*)d_in[6];
    const float* ob2   = (const float*)d_in[7];
    const float* mw1   = (const float*)d_in[8];
    const float* mb1   = (const float*)d_in[9];
    const float* mw2   = (const float*)d_in[10];
    const float* mb2   = (const float*)d_in[11];
    const float* iw    = (const float*)d_in[12];
    const float* ib    = (const float*)d_in[13];

    int n = in_sizes[1];
    int B = (out_size - 4 * n) / 33;
    if (B < 1) B = 1;
    if (B > 64) B = 64;

    float* out        = (float*)d_out;
    float* out_off    = out;
    float* out_mask   = out + (size_t)3 * n;
    float* out_pooled = out + (size_t)4 * n;
    float* out_iou    = out_pooled + (size_t)B * C;

    int tiles  = (n + TP - 1) / TP;
    int blocks = 608;
    int warps  = blocks * WPB;
    int tpw    = (tiles + warps - 1) / warps;

    zero_kernel<<<1, 1024>>>(B);
    pass1_kernel<<<blocks, 32 * WPB>>>(feats, bidx, w1, b1, mw1, mb1, mw2, mb2,
                                       out_mask, n, tiles, tpw);
    finalize_kernel<<<1, 32>>>(w1, b1, gamma, beta, iw, ib,
                               out_pooled, out_iou, n, B);
    pass2_kernel<<<blocks, 32 * WPB>>>(feats, w2, ob2, out_off, n, tiles, tpw);
}